// round 4
// baseline (speedup 1.0000x reference)
#include <cuda_runtime.h>

#define TT   2048
#define BB   2048
#define HH   32
#define DF   8
#define DS   24
#define GPB  4                 // 4-batch groups per block
#define NW   (GPB * 3)         // 12 warps: (A,B,C) x 4 groups
#define NTHR (NW * 32)         // 384 threads
#define NBLK (BB / (GPB * 4))  // 128 blocks

typedef unsigned long long u64;

__device__ __forceinline__ u64 dup2(float w) {
    u64 d; asm("mov.b64 %0, {%1, %1};" : "=l"(d) : "f"(w)); return d;
}
__device__ __forceinline__ void unpack2(u64 v, float &a, float &b) {
    asm("mov.b64 {%0, %1}, %2;" : "=f"(a), "=f"(b) : "l"(v));
}
__device__ __forceinline__ u64 pack2(float a, float b) {
    u64 d; asm("mov.b64 %0, {%1, %2};" : "=l"(d) : "f"(a), "f"(b)); return d;
}
__device__ __forceinline__ void fma2(u64 &acc, u64 a, u64 b) {
    asm("fma.rn.f32x2 %0, %1, %2, %0;" : "+l"(acc) : "l"(a), "l"(b));
}
// broadcast a 64-bit pack (2 f32) from lane src: 2x SHFL.32
__device__ __forceinline__ u64 shfl2(u64 v, int src) {
    unsigned lo = (unsigned)v, hi = (unsigned)(v >> 32);
    lo = __shfl_sync(0xffffffffu, lo, src);
    hi = __shfl_sync(0xffffffffu, hi, src);
    return ((u64)hi << 32) | (u64)lo;
}
__device__ __forceinline__ float tanh_fast(float x) {
    float e = __expf(2.0f * x);
    return 1.0f - __fdividef(2.0f, e + 1.0f);
}

struct GroupSW {
    float4 xA[2][DF];   // staged x_f, ping-pong
    float4 xB[2][DF];   // staged x_p
    float4 xC[2][DS];   // staged x_s (24 real rows only)
};

__global__ void __launch_bounds__(NTHR, 1) chive_kernel(
    const float* __restrict__ frnn, const float* __restrict__ phrnn, const float* __restrict__ syl,
    const float* __restrict__ Wxf, const float* __restrict__ Whf, const float* __restrict__ bfv,
    const float* __restrict__ Wxp, const float* __restrict__ Whp, const float* __restrict__ bpv,
    const float* __restrict__ Wxs, const float* __restrict__ Whs, const float* __restrict__ bsv,
    const int* __restrict__ fclk, const int* __restrict__ pclk, const int* __restrict__ sfreq,
    float* __restrict__ out)
{
    __shared__ GroupSW sw[GPB];
    __shared__ unsigned char flags[TT];

    const int tid  = threadIdx.x;
    const int wid  = tid >> 5;
    const int lane = tid & 31;
    const int grp  = wid / 3;
    const int role = wid % 3;      // 0 = f-cell+row0, 1 = p-cell+row1, 2 = row2
    const int j    = lane;

    // ---- warp-uniform update masks, depend only on t ----
    for (int t = tid; t < TT; t += NTHR) {
        int uf = ((t % (fclk[t] + 1)) == 0) ? 1 : 0;
        int up = ((t % (pclk[t] + 1)) == 0) ? 1 : 0;
        int us = (sfreq[t] == 1) ? 1 : 0;
        flags[t] = (unsigned char)(uf | (up << 1) | (us << 2));
    }
    __syncthreads();

    GroupSW& G = sw[grp];
    const int b0 = (blockIdx.x * GPB + grp) * 4;   // this group's 4 batch rows

    // ---- syl weight column j (all roles) ----
    float wsh[HH];
#pragma unroll
    for (int i = 0; i < HH; i++) wsh[i] = Whs[i * HH + j];
    const float bs_ = bsv[j];

    // ---- recurrent state in registers: lane j holds 4-batch pack for unit j ----
    u64 s0 = 0, s1 = 0;            // this warp's h_s row

    if (role < 2) {
        // ============ warp A / B: clockwork cell + its syl row (all-register) ======
        const float* xsrc = (role == 0) ? frnn : phrnn;
        const float* Wx   = (role == 0) ? Wxf  : Wxp;
        const float* Wh   = (role == 0) ? Whf  : Whp;
        const float* bv   = (role == 0) ? bfv  : bpv;
        float4 (*xbuf)[DF] = (role == 0) ? G.xA : G.xB;
        const unsigned bit = 1u << role;

        float wx[DF], wh[HH], wsx[HH];
#pragma unroll
        for (int k = 0; k < DF; k++) wx[k] = Wx[k * HH + j];
#pragma unroll
        for (int i = 0; i < HH; i++) { wh[i] = Wh[i * HH + j]; wsx[i] = Wxs[i * HH + j]; }
        const float bc = bv[j];

        u64 h0 = 0, h1 = 0;                     // cell hidden state (regs)
        u64 c0 = dup2(bs_), c1 = dup2(bs_);     // cached  bs + h @ Wx_s

        // staging: lane -> batch (lane>>3), feature (lane&7)
        const float* px = xsrc + (size_t)(b0 + (lane >> 3)) * DF + (lane & 7);
        float* xd = (float*)xbuf + (lane & 7) * 4 + (lane >> 3);
        const size_t str = (size_t)BB * DF;

        float v = px[0];                        // prefetch t=0
        for (int t = 0; t < TT; t++) {
            const int par = t & 1;
            xd[par * 32] = v;
            const size_t tn = (t + 1 < TT) ? (size_t)(t + 1) : (size_t)(TT - 1);
            v = px[tn * str];                   // prefetch next step
            const unsigned fl = flags[t];
            __syncwarp();                       // staged x visible

            if (fl & bit) {                     // ---- clockwork cell update ----
                u64 a = dup2(bc), b = dup2(bc);
                const ulonglong2* xv = (const ulonglong2*)xbuf[par];
#pragma unroll
                for (int k = 0; k < DF; k++) {
                    ulonglong2 x = xv[k]; u64 wd = dup2(wx[k]);
                    fma2(a, x.x, wd); fma2(b, x.y, wd);
                }
#pragma unroll
                for (int i = 0; i < HH; i++) {  // h-part via register shuffles
                    u64 p0 = shfl2(h0, i), p1 = shfl2(h1, i);
                    u64 wd = dup2(wh[i]);
                    fma2(a, p0, wd); fma2(b, p1, wd);
                }
                float q0, q1, q2, q3; unpack2(a, q0, q1); unpack2(b, q2, q3);
                h0 = pack2(tanh_fast(q0), tanh_fast(q1));
                h1 = pack2(tanh_fast(q2), tanh_fast(q3));
                // refresh cached  c = bs + h_new @ Wx_s  (shuffles of fresh regs)
                u64 ca = dup2(bs_), cb = dup2(bs_);
#pragma unroll
                for (int i = 0; i < HH; i++) {
                    u64 p0 = shfl2(h0, i), p1 = shfl2(h1, i);
                    u64 wd = dup2(wsx[i]);
                    fma2(ca, p0, wd); fma2(cb, p1, wd);
                }
                c0 = ca; c1 = cb;
            }
            if (fl & 4) {                       // ---- syl row update ----
                u64 a = c0, b = c1;             // bs + h @ Wx_s cached
#pragma unroll
                for (int i = 0; i < HH; i++) {
                    u64 p0 = shfl2(s0, i), p1 = shfl2(s1, i);
                    u64 wd = dup2(wsh[i]);
                    fma2(a, p0, wd); fma2(b, p1, wd);
                }
                float q0, q1, q2, q3; unpack2(a, q0, q1); unpack2(b, q2, q3);
                s0 = pack2(tanh_fast(q0), tanh_fast(q1));
                s1 = pack2(tanh_fast(q2), tanh_fast(q3));
            }
        }
    } else {
        // ============ warp C: x_s-driven syl row (state in regs) ==================
        float wsx[DS];
#pragma unroll
        for (int i = 0; i < DS; i++) wsx[i] = Wxs[i * HH + j];

        const int fl0 = lane, fl1 = lane + 32, fl2 = lane + 64;   // 96 scalars
        const float* p0 = syl + (size_t)(b0 + fl0 / 24) * DS + (fl0 % 24);
        const float* p1 = syl + (size_t)(b0 + fl1 / 24) * DS + (fl1 % 24);
        const float* p2 = syl + (size_t)(b0 + fl2 / 24) * DS + (fl2 % 24);
        float* d0 = (float*)G.xC + (fl0 % 24) * 4 + (fl0 / 24);
        float* d1 = (float*)G.xC + (fl1 % 24) * 4 + (fl1 / 24);
        float* d2 = (float*)G.xC + (fl2 % 24) * 4 + (fl2 / 24);
        const size_t str = (size_t)BB * DS;

        float v0 = p0[0], v1 = p1[0], v2 = p2[0];
        for (int t = 0; t < TT; t++) {
            const int par = t & 1;
            d0[par * 96] = v0; d1[par * 96] = v1; d2[par * 96] = v2;
            const size_t tn = (t + 1 < TT) ? (size_t)(t + 1) : (size_t)(TT - 1);
            v0 = p0[tn * str]; v1 = p1[tn * str]; v2 = p2[tn * str];
            const unsigned fl = flags[t];
            __syncwarp();

            if (fl & 4) {
                u64 a = dup2(bs_), b = dup2(bs_);
                const ulonglong2* xv = (const ulonglong2*)G.xC[par];
#pragma unroll
                for (int i = 0; i < DS; i++) {          // only 24 real rows
                    ulonglong2 x = xv[i]; u64 wd = dup2(wsx[i]);
                    fma2(a, x.x, wd); fma2(b, x.y, wd);
                }
#pragma unroll
                for (int i = 0; i < HH; i++) {          // s-part via shuffles
                    u64 q0 = shfl2(s0, i), q1 = shfl2(s1, i);
                    u64 wd = dup2(wsh[i]);
                    fma2(a, q0, wd); fma2(b, q1, wd);
                }
                float q0, q1, q2, q3; unpack2(a, q0, q1); unpack2(b, q2, q3);
                s0 = pack2(tanh_fast(q0), tanh_fast(q1));
                s1 = pack2(tanh_fast(q2), tanh_fast(q3));
            }
        }
    }

    // ---- output: h_s rows straight from registers ----
    {
        float q0, q1, q2, q3; unpack2(s0, q0, q1); unpack2(s1, q2, q3);
        out[((size_t)role * BB + b0 + 0) * HH + j] = q0;
        out[((size_t)role * BB + b0 + 1) * HH + j] = q1;
        out[((size_t)role * BB + b0 + 2) * HH + j] = q2;
        out[((size_t)role * BB + b0 + 3) * HH + j] = q3;
    }
}

extern "C" void kernel_launch(void* const* d_in, const int* in_sizes, int n_in,
                              void* d_out, int out_size)
{
    (void)in_sizes; (void)n_in; (void)out_size;
    chive_kernel<<<NBLK, NTHR>>>(
        (const float*)d_in[0],  (const float*)d_in[1],  (const float*)d_in[2],
        (const float*)d_in[3],  (const float*)d_in[4],  (const float*)d_in[5],
        (const float*)d_in[6],  (const float*)d_in[7],  (const float*)d_in[8],
        (const float*)d_in[9],  (const float*)d_in[10], (const float*)d_in[11],
        (const int*)d_in[12],   (const int*)d_in[13],   (const int*)d_in[14],
        (float*)d_out);
}

// round 7
// speedup vs baseline: 1.5605x; 1.5605x over previous
#include <cuda_runtime.h>

#define TT   2048
#define BB   2048
#define HH   32
#define DF   8
#define DS   24
#define GPB  4                 // 4-batch groups per block
#define NW   (GPB * 3)         // 12 warps: (A,B,C) x 4 groups
#define NTHR (NW * 32)         // 384 threads
#define NBLK (BB / (GPB * 4))  // 128 blocks

typedef unsigned long long u64;

__device__ __forceinline__ u64 dup2(float w) {
    u64 d; asm("mov.b64 %0, {%1, %1};" : "=l"(d) : "f"(w)); return d;
}
__device__ __forceinline__ void unpack2(u64 v, float &a, float &b) {
    asm("mov.b64 {%0, %1}, %2;" : "=f"(a), "=f"(b) : "l"(v));
}
__device__ __forceinline__ void fma2(u64 &acc, u64 a, u64 b) {
    asm("fma.rn.f32x2 %0, %1, %2, %0;" : "+l"(acc) : "l"(a), "l"(b));
}
__device__ __forceinline__ u64 add2(u64 x, u64 y) {
    u64 r; asm("add.rn.f32x2 %0, %1, %2;" : "=l"(r) : "l"(x), "l"(y)); return r;
}
__device__ __forceinline__ float tanh_fast(float x) {
    float e = __expf(2.0f * x);
    return 1.0f - __fdividef(2.0f, e + 1.0f);
}

struct GroupSW {
    float4 hA[HH];                 // h_f  (warp A)
    float4 hB[HH];                 // h_p  (warp B)
    float4 s0[HH], s1[HH], s2[HH]; // h_s rows (A, B, C)
    float4 xA[2][DF], xB[2][DF];   // staged x_f / x_p, ping-pong
    float4 xC[2][DS];              // staged x_s (24 real rows)
};

__global__ void __launch_bounds__(NTHR, 1) chive_kernel(
    const float* __restrict__ frnn, const float* __restrict__ phrnn, const float* __restrict__ syl,
    const float* __restrict__ Wxf, const float* __restrict__ Whf, const float* __restrict__ bfv,
    const float* __restrict__ Wxp, const float* __restrict__ Whp, const float* __restrict__ bpv,
    const float* __restrict__ Wxs, const float* __restrict__ Whs, const float* __restrict__ bsv,
    const int* __restrict__ fclk, const int* __restrict__ pclk, const int* __restrict__ sfreq,
    float* __restrict__ out)
{
    __shared__ GroupSW sw[GPB];
    __shared__ unsigned char flags[TT];

    const int tid  = threadIdx.x;
    const int wid  = tid >> 5;
    const int lane = tid & 31;
    const int grp  = wid / 3;
    const int role = wid % 3;      // 0 = f-cell+row0, 1 = p-cell+row1, 2 = row2
    const int j    = lane;

    // ---- zero all state + staging ----
    for (int i = tid; i < (int)(sizeof(GroupSW) / 4) * GPB; i += NTHR)
        ((float*)sw)[i] = 0.0f;

    // ---- warp-uniform update masks, depend only on t ----
    for (int t = tid; t < TT; t += NTHR) {
        int uf = ((t % (fclk[t] + 1)) == 0) ? 1 : 0;
        int up = ((t % (pclk[t] + 1)) == 0) ? 1 : 0;
        int us = (sfreq[t] == 1) ? 1 : 0;
        flags[t] = (unsigned char)(uf | (up << 1) | (us << 2));
    }
    __syncthreads();

    GroupSW& G = sw[grp];
    const int b0 = (blockIdx.x * GPB + grp) * 4;   // this group's 4 batch rows

    // ---- syl weight column j (all roles) ----
    float wsh[HH];
#pragma unroll
    for (int i = 0; i < HH; i++) wsh[i] = Whs[i * HH + j];
    const float bs_ = bsv[j];

    float4* srow = (role == 0) ? G.s0 : (role == 1) ? G.s1 : G.s2;

    if (role < 2) {
        // ============ warp A / B: clockwork cell + its syl row ====================
        const float* xsrc = (role == 0) ? frnn : phrnn;
        const float* Wx   = (role == 0) ? Wxf  : Wxp;
        const float* Wh   = (role == 0) ? Whf  : Whp;
        const float* bv   = (role == 0) ? bfv  : bpv;
        float4* hst       = (role == 0) ? G.hA : G.hB;
        float4 (*xbuf)[DF] = (role == 0) ? G.xA : G.xB;
        const unsigned bit = 1u << role;

        float wx[DF], wh[HH], wsx[HH];
#pragma unroll
        for (int k = 0; k < DF; k++) wx[k] = Wx[k * HH + j];
#pragma unroll
        for (int i = 0; i < HH; i++) { wh[i] = Wh[i * HH + j]; wsx[i] = Wxs[i * HH + j]; }
        const float bc = bv[j];

        // staging: lane -> batch (lane>>3), feature (lane&7)
        const float* px = xsrc + (size_t)(b0 + (lane >> 3)) * DF + (lane & 7);
        float* xd = (float*)xbuf + (lane & 7) * 4 + (lane >> 3);
        const size_t str = (size_t)BB * DF;

        float v = px[0];                      // prefetch t=0
        for (int t = 0; t < TT; t++) {
            const int par = t & 1;
            xd[par * 32] = v;
            const size_t tn = (t + 1 < TT) ? (size_t)(t + 1) : (size_t)(TT - 1);
            v = px[tn * str];                 // prefetch next step
            const unsigned fl = flags[t];
            __syncwarp();                     // staged x visible

            if (fl & bit) {                   // ---- clockwork cell update ----
                // 6 independent accumulator chains (ptxas can't reassociate
                // "+l" fma chains, so we break the RAW chain explicitly)
                u64 a = dup2(bc), b = dup2(bc);
                u64 c = 0, d = 0, e = 0, f = 0;
                const ulonglong2* xv = (const ulonglong2*)xbuf[par];
#pragma unroll
                for (int k = 0; k < DF; k++) {
                    ulonglong2 x = xv[k]; u64 wd = dup2(wx[k]);
                    fma2(a, x.x, wd); fma2(b, x.y, wd);
                }
                const ulonglong2* hv = (const ulonglong2*)hst;
#pragma unroll
                for (int i = 0; i < HH / 2; i++) {
                    ulonglong2 h = hv[i]; u64 wd = dup2(wh[i]);
                    fma2(c, h.x, wd); fma2(d, h.y, wd);
                }
#pragma unroll
                for (int i = HH / 2; i < HH; i++) {
                    ulonglong2 h = hv[i]; u64 wd = dup2(wh[i]);
                    fma2(e, h.x, wd); fma2(f, h.y, wd);
                }
                u64 ra = add2(a, add2(c, e));
                u64 rb = add2(b, add2(d, f));
                float q0, q1, q2, q3; unpack2(ra, q0, q1); unpack2(rb, q2, q3);
                float4 nf = make_float4(tanh_fast(q0), tanh_fast(q1),
                                        tanh_fast(q2), tanh_fast(q3));
                __syncwarp();                 // all lanes done reading old h
                hst[j] = nf;
            }
            if (fl & 4) {                     // ---- syl row update ----
                __syncwarp();                 // h writes visible
                // 8 independent chains: 4 for h@Wx_s, 4 for s@Wh_s
                u64 a = dup2(bs_), b = dup2(bs_);
                u64 c = 0, d = 0, e = 0, f = 0, g = 0, k2 = 0;
                const ulonglong2* hv = (const ulonglong2*)hst;
#pragma unroll
                for (int i = 0; i < HH / 2; i++) {
                    ulonglong2 h = hv[i]; u64 wd = dup2(wsx[i]);
                    fma2(a, h.x, wd); fma2(b, h.y, wd);
                }
#pragma unroll
                for (int i = HH / 2; i < HH; i++) {
                    ulonglong2 h = hv[i]; u64 wd = dup2(wsx[i]);
                    fma2(c, h.x, wd); fma2(d, h.y, wd);
                }
                const ulonglong2* rv = (const ulonglong2*)srow;
#pragma unroll
                for (int i = 0; i < HH / 2; i++) {
                    ulonglong2 h = rv[i]; u64 wd = dup2(wsh[i]);
                    fma2(e, h.x, wd); fma2(f, h.y, wd);
                }
#pragma unroll
                for (int i = HH / 2; i < HH; i++) {
                    ulonglong2 h = rv[i]; u64 wd = dup2(wsh[i]);
                    fma2(g, h.x, wd); fma2(k2, h.y, wd);
                }
                u64 ra = add2(add2(a, c), add2(e, g));
                u64 rb = add2(add2(b, d), add2(f, k2));
                float q0, q1, q2, q3; unpack2(ra, q0, q1); unpack2(rb, q2, q3);
                float4 n = make_float4(tanh_fast(q0), tanh_fast(q1),
                                       tanh_fast(q2), tanh_fast(q3));
                __syncwarp();                 // all lanes done reading old srow
                srow[j] = n;
            }
        }
    } else {
        // ============ warp C: x_s-driven syl row ==================================
        float wsx[DS];
#pragma unroll
        for (int i = 0; i < DS; i++) wsx[i] = Wxs[i * HH + j];

        const int fl0 = lane, fl1 = lane + 32, fl2 = lane + 64;   // 96 scalars
        const float* p0 = syl + (size_t)(b0 + fl0 / 24) * DS + (fl0 % 24);
        const float* p1 = syl + (size_t)(b0 + fl1 / 24) * DS + (fl1 % 24);
        const float* p2 = syl + (size_t)(b0 + fl2 / 24) * DS + (fl2 % 24);
        float* d0 = (float*)G.xC + (fl0 % 24) * 4 + (fl0 / 24);
        float* d1 = (float*)G.xC + (fl1 % 24) * 4 + (fl1 / 24);
        float* d2 = (float*)G.xC + (fl2 % 24) * 4 + (fl2 / 24);
        const size_t str = (size_t)BB * DS;

        float v0 = p0[0], v1 = p1[0], v2 = p2[0];
        for (int t = 0; t < TT; t++) {
            const int par = t & 1;
            d0[par * 96] = v0; d1[par * 96] = v1; d2[par * 96] = v2;
            const size_t tn = (t + 1 < TT) ? (size_t)(t + 1) : (size_t)(TT - 1);
            v0 = p0[tn * str]; v1 = p1[tn * str]; v2 = p2[tn * str];
            const unsigned fl = flags[t];
            __syncwarp();

            if (fl & 4) {
                // 8 chains: 4 for x-part (24 iters), 4 for s-part (32 iters)
                u64 a = dup2(bs_), b = dup2(bs_);
                u64 c = 0, d = 0, e = 0, f = 0, g = 0, k2 = 0;
                const ulonglong2* xv = (const ulonglong2*)G.xC[par];
#pragma unroll
                for (int i = 0; i < DS / 2; i++) {
                    ulonglong2 x = xv[i]; u64 wd = dup2(wsx[i]);
                    fma2(a, x.x, wd); fma2(b, x.y, wd);
                }
#pragma unroll
                for (int i = DS / 2; i < DS; i++) {
                    ulonglong2 x = xv[i]; u64 wd = dup2(wsx[i]);
                    fma2(c, x.x, wd); fma2(d, x.y, wd);
                }
                const ulonglong2* rv = (const ulonglong2*)srow;
#pragma unroll
                for (int i = 0; i < HH / 2; i++) {
                    ulonglong2 h = rv[i]; u64 wd = dup2(wsh[i]);
                    fma2(e, h.x, wd); fma2(f, h.y, wd);
                }
#pragma unroll
                for (int i = HH / 2; i < HH; i++) {
                    ulonglong2 h = rv[i]; u64 wd = dup2(wsh[i]);
                    fma2(g, h.x, wd); fma2(k2, h.y, wd);
                }
                u64 ra = add2(add2(a, c), add2(e, g));
                u64 rb = add2(add2(b, d), add2(f, k2));
                float q0, q1, q2, q3; unpack2(ra, q0, q1); unpack2(rb, q2, q3);
                float4 n = make_float4(tanh_fast(q0), tanh_fast(q1),
                                       tanh_fast(q2), tanh_fast(q3));
                __syncwarp();
                srow[j] = n;
            }
        }
    }

    // ---- output: each warp writes its own h_s row ----
    {
        float4 vv = srow[j];
        out[((size_t)role * BB + b0 + 0) * HH + j] = vv.x;
        out[((size_t)role * BB + b0 + 1) * HH + j] = vv.y;
        out[((size_t)role * BB + b0 + 2) * HH + j] = vv.z;
        out[((size_t)role * BB + b0 + 3) * HH + j] = vv.w;
    }
}

extern "C" void kernel_launch(void* const* d_in, const int* in_sizes, int n_in,
                              void* d_out, int out_size)
{
    (void)in_sizes; (void)n_in; (void)out_size;
    chive_kernel<<<NBLK, NTHR>>>(
        (const float*)d_in[0],  (const float*)d_in[1],  (const float*)d_in[2],
        (const float*)d_in[3],  (const float*)d_in[4],  (const float*)d_in[5],
        (const float*)d_in[6],  (const float*)d_in[7],  (const float*)d_in[8],
        (const float*)d_in[9],  (const float*)d_in[10], (const float*)d_in[11],
        (const int*)d_in[12],   (const int*)d_in[13],   (const int*)d_in[14],
        (float*)d_out);
}

// round 8
// speedup vs baseline: 1.7474x; 1.1198x over previous
#include <cuda_runtime.h>

#define TT   2048
#define BB   2048
#define HH   32
#define DF   8
#define DS   24
#define GPB  4                 // 4-batch groups per block
#define NW   (GPB * 3)         // 12 warps: (A,B,C) x 4 groups
#define NTHR (NW * 32)         // 384 threads
#define NBLK (BB / (GPB * 4))  // 128 blocks

typedef unsigned long long u64;

__device__ __forceinline__ u64 dup2(float w) {
    u64 d; asm("mov.b64 %0, {%1, %1};" : "=l"(d) : "f"(w)); return d;
}
__device__ __forceinline__ void unpack2(u64 v, float &a, float &b) {
    asm("mov.b64 {%0, %1}, %2;" : "=f"(a), "=f"(b) : "l"(v));
}
__device__ __forceinline__ void fma2(u64 &acc, u64 a, u64 b) {
    asm("fma.rn.f32x2 %0, %1, %2, %0;" : "+l"(acc) : "l"(a), "l"(b));
}
__device__ __forceinline__ u64 add2(u64 x, u64 y) {
    u64 r; asm("add.rn.f32x2 %0, %1, %2;" : "=l"(r) : "l"(x), "l"(y)); return r;
}
__device__ __forceinline__ float tanh_fast(float x) {
    float e = __expf(2.0f * x);
    return 1.0f - __fdividef(2.0f, e + 1.0f);
}

struct GroupSW {
    float4 hA[HH];                 // h_f  (warp A)
    float4 hB[HH];                 // h_p  (warp B)
    float4 s0[HH], s1[HH], s2[HH]; // h_s rows (A, B, C)
    float4 xA[DF], xB[DF];         // staged x_f / x_p (read same step as written)
    float4 xC[DS];                 // staged x_s
};

__global__ void __launch_bounds__(NTHR, 1) chive_kernel(
    const float* __restrict__ frnn, const float* __restrict__ phrnn, const float* __restrict__ syl,
    const float* __restrict__ Wxf, const float* __restrict__ Whf, const float* __restrict__ bfv,
    const float* __restrict__ Wxp, const float* __restrict__ Whp, const float* __restrict__ bpv,
    const float* __restrict__ Wxs, const float* __restrict__ Whs, const float* __restrict__ bsv,
    const int* __restrict__ fclk, const int* __restrict__ pclk, const int* __restrict__ sfreq,
    float* __restrict__ out)
{
    __shared__ GroupSW sw[GPB];
    __shared__ unsigned char flags[TT];

    const int tid  = threadIdx.x;
    const int wid  = tid >> 5;
    const int lane = tid & 31;
    const int grp  = wid / 3;
    const int role = wid % 3;      // 0 = f-cell+row0, 1 = p-cell+row1, 2 = row2
    const int j    = lane;

    // ---- zero all state + staging ----
    for (int i = tid; i < (int)(sizeof(GroupSW) / 4) * GPB; i += NTHR)
        ((float*)sw)[i] = 0.0f;

    // ---- warp-uniform update masks, depend only on t ----
    for (int t = tid; t < TT; t += NTHR) {
        int uf = ((t % (fclk[t] + 1)) == 0) ? 1 : 0;
        int up = ((t % (pclk[t] + 1)) == 0) ? 1 : 0;
        int us = (sfreq[t] == 1) ? 1 : 0;
        flags[t] = (unsigned char)(uf | (up << 1) | (us << 2));
    }
    __syncthreads();

    GroupSW& G = sw[grp];
    const int b0 = (blockIdx.x * GPB + grp) * 4;   // this group's 4 batch rows

    // ---- syl weight column j (all roles) ----
    float wsh[HH];
#pragma unroll
    for (int i = 0; i < HH; i++) wsh[i] = Whs[i * HH + j];
    const float bs_ = bsv[j];

    float4* srow = (role == 0) ? G.s0 : (role == 1) ? G.s1 : G.s2;

    if (role < 2) {
        // ============ warp A / B: clockwork cell + its syl row ====================
        const float* xsrc = (role == 0) ? frnn : phrnn;
        const float* Wx   = (role == 0) ? Wxf  : Wxp;
        const float* Wh   = (role == 0) ? Whf  : Whp;
        const float* bv   = (role == 0) ? bfv  : bpv;
        float4* hst       = (role == 0) ? G.hA : G.hB;
        float4* xbuf      = (role == 0) ? G.xA : G.xB;
        const unsigned bit = 1u << role;

        float wx[DF], wh[HH], wsx[HH];
#pragma unroll
        for (int k = 0; k < DF; k++) wx[k] = Wx[k * HH + j];
#pragma unroll
        for (int i = 0; i < HH; i++) { wh[i] = Wh[i * HH + j]; wsx[i] = Wxs[i * HH + j]; }
        const float bc = bv[j];

        // cached  c = bs + h @ Wx_s  (h = 0 initially)
        u64 c0 = dup2(bs_), c1 = dup2(bs_);

        // staging: lane -> batch (lane>>3), feature (lane&7)
        const float* px = xsrc + (size_t)(b0 + (lane >> 3)) * DF + (lane & 7);
        float* xd = (float*)xbuf + (lane & 7) * 4 + (lane >> 3);
        const size_t str = (size_t)BB * DF;

        unsigned fl = flags[0];
        float v = (fl & bit) ? px[0] : 0.0f;   // x[0] only if needed
        for (int t = 0; t < TT; t++) {
            const unsigned fln = (t + 1 < TT) ? (unsigned)flags[t + 1] : 0u;

            if (fl & bit) {                    // ---- clockwork cell update ----
                xd[0] = v;                     // stage x[t]
                __syncwarp();                  // x visible; prior hst write visible
                u64 a = dup2(bc), b = dup2(bc);
                u64 c = 0, d = 0, e = 0, f = 0;
                const ulonglong2* xv = (const ulonglong2*)xbuf;
#pragma unroll
                for (int k = 0; k < DF; k++) {
                    ulonglong2 x = xv[k]; u64 wd = dup2(wx[k]);
                    fma2(a, x.x, wd); fma2(b, x.y, wd);
                }
                const ulonglong2* hv = (const ulonglong2*)hst;
#pragma unroll
                for (int i = 0; i < HH / 2; i++) {
                    ulonglong2 h = hv[i]; u64 wd = dup2(wh[i]);
                    fma2(c, h.x, wd); fma2(d, h.y, wd);
                }
#pragma unroll
                for (int i = HH / 2; i < HH; i++) {
                    ulonglong2 h = hv[i]; u64 wd = dup2(wh[i]);
                    fma2(e, h.x, wd); fma2(f, h.y, wd);
                }
                u64 ra = add2(a, add2(c, e));
                u64 rb = add2(b, add2(d, f));
                float q0, q1, q2, q3; unpack2(ra, q0, q1); unpack2(rb, q2, q3);
                float4 nf = make_float4(tanh_fast(q0), tanh_fast(q1),
                                        tanh_fast(q2), tanh_fast(q3));
                __syncwarp();                  // all lanes done reading old h / x
                hst[j] = nf;
                __syncwarp();                  // new h visible
                // refresh cached  c = bs + h_new @ Wx_s
                u64 ca = dup2(bs_), cb = dup2(bs_);
                u64 cc = 0, cd = 0;
#pragma unroll
                for (int i = 0; i < HH / 2; i++) {
                    ulonglong2 h = hv[i]; u64 wd = dup2(wsx[i]);
                    fma2(ca, h.x, wd); fma2(cb, h.y, wd);
                }
#pragma unroll
                for (int i = HH / 2; i < HH; i++) {
                    ulonglong2 h = hv[i]; u64 wd = dup2(wsx[i]);
                    fma2(cc, h.x, wd); fma2(cd, h.y, wd);
                }
                c0 = add2(ca, cc); c1 = add2(cb, cd);
            }
            if (fln & bit)                     // prefetch x[t+1] only if needed
                v = px[(size_t)(t + 1) * str];

            if (fl & 4) {                      // ---- syl row update ----
                __syncwarp();                  // prior srow write visible
                u64 a = c0, b = c1;            // cached bs + h@Wx_s
                u64 e = 0, f = 0, g = 0, k2 = 0;
                const ulonglong2* rv = (const ulonglong2*)srow;
#pragma unroll
                for (int i = 0; i < HH / 2; i++) {
                    ulonglong2 h = rv[i]; u64 wd = dup2(wsh[i]);
                    fma2(e, h.x, wd); fma2(f, h.y, wd);
                }
#pragma unroll
                for (int i = HH / 2; i < HH; i++) {
                    ulonglong2 h = rv[i]; u64 wd = dup2(wsh[i]);
                    fma2(g, h.x, wd); fma2(k2, h.y, wd);
                }
                u64 ra = add2(a, add2(e, g));
                u64 rb = add2(b, add2(f, k2));
                float q0, q1, q2, q3; unpack2(ra, q0, q1); unpack2(rb, q2, q3);
                float4 n = make_float4(tanh_fast(q0), tanh_fast(q1),
                                       tanh_fast(q2), tanh_fast(q3));
                __syncwarp();                  // all lanes done reading old srow
                srow[j] = n;
            }
            fl = fln;
        }
    } else {
        // ============ warp C: x_s-driven syl row ==================================
        float wsx[DS];
#pragma unroll
        for (int i = 0; i < DS; i++) wsx[i] = Wxs[i * HH + j];

        const int fl0 = lane, fl1 = lane + 32, fl2 = lane + 64;   // 96 scalars
        const float* p0 = syl + (size_t)(b0 + fl0 / 24) * DS + (fl0 % 24);
        const float* p1 = syl + (size_t)(b0 + fl1 / 24) * DS + (fl1 % 24);
        const float* p2 = syl + (size_t)(b0 + fl2 / 24) * DS + (fl2 % 24);
        float* d0 = (float*)G.xC + (fl0 % 24) * 4 + (fl0 / 24);
        float* d1 = (float*)G.xC + (fl1 % 24) * 4 + (fl1 / 24);
        float* d2 = (float*)G.xC + (fl2 % 24) * 4 + (fl2 / 24);
        const size_t str = (size_t)BB * DS;

        unsigned fl = flags[0];
        float v0 = 0.f, v1 = 0.f, v2 = 0.f;
        if (fl & 4) { v0 = p0[0]; v1 = p1[0]; v2 = p2[0]; }
        for (int t = 0; t < TT; t++) {
            const unsigned fln = (t + 1 < TT) ? (unsigned)flags[t + 1] : 0u;

            if (fl & 4) {
                d0[0] = v0; d1[0] = v1; d2[0] = v2;   // stage x_s[t]
                __syncwarp();                          // staged x + prior srow visible
                u64 a = dup2(bs_), b = dup2(bs_);
                u64 c = 0, d = 0, e = 0, f = 0, g = 0, k2 = 0;
                const ulonglong2* xv = (const ulonglong2*)G.xC;
#pragma unroll
                for (int i = 0; i < DS / 2; i++) {
                    ulonglong2 x = xv[i]; u64 wd = dup2(wsx[i]);
                    fma2(a, x.x, wd); fma2(b, x.y, wd);
                }
#pragma unroll
                for (int i = DS / 2; i < DS; i++) {
                    ulonglong2 x = xv[i]; u64 wd = dup2(wsx[i]);
                    fma2(c, x.x, wd); fma2(d, x.y, wd);
                }
                const ulonglong2* rv = (const ulonglong2*)srow;
#pragma unroll
                for (int i = 0; i < HH / 2; i++) {
                    ulonglong2 h = rv[i]; u64 wd = dup2(wsh[i]);
                    fma2(e, h.x, wd); fma2(f, h.y, wd);
                }
#pragma unroll
                for (int i = HH / 2; i < HH; i++) {
                    ulonglong2 h = rv[i]; u64 wd = dup2(wsh[i]);
                    fma2(g, h.x, wd); fma2(k2, h.y, wd);
                }
                u64 ra = add2(add2(a, c), add2(e, g));
                u64 rb = add2(add2(b, d), add2(f, k2));
                float q0, q1, q2, q3; unpack2(ra, q0, q1); unpack2(rb, q2, q3);
                float4 n = make_float4(tanh_fast(q0), tanh_fast(q1),
                                       tanh_fast(q2), tanh_fast(q3));
                __syncwarp();                  // reads done (x WAR + srow WAR)
                srow[j] = n;
            }
            if (fln & 4) {                     // prefetch x_s[t+1] only if needed
                const size_t o = (size_t)(t + 1) * str;
                v0 = p0[o]; v1 = p1[o]; v2 = p2[o];
            }
            fl = fln;
        }
    }

    // ---- output: each warp writes its own h_s row ----
    {
        float4 vv = srow[j];
        out[((size_t)role * BB + b0 + 0) * HH + j] = vv.x;
        out[((size_t)role * BB + b0 + 1) * HH + j] = vv.y;
        out[((size_t)role * BB + b0 + 2) * HH + j] = vv.z;
        out[((size_t)role * BB + b0 + 3) * HH + j] = vv.w;
    }
}

extern "C" void kernel_launch(void* const* d_in, const int* in_sizes, int n_in,
                              void* d_out, int out_size)
{
    (void)in_sizes; (void)n_in; (void)out_size;
    chive_kernel<<<NBLK, NTHR>>>(
        (const float*)d_in[0],  (const float*)d_in[1],  (const float*)d_in[2],
        (const float*)d_in[3],  (const float*)d_in[4],  (const float*)d_in[5],
        (const float*)d_in[6],  (const float*)d_in[7],  (const float*)d_in[8],
        (const float*)d_in[9],  (const float*)d_in[10], (const float*)d_in[11],
        (const int*)d_in[12],   (const int*)d_in[13],   (const int*)d_in[14],
        (float*)d_out);
}

// round 9
// speedup vs baseline: 1.8073x; 1.0343x over previous
#include <cuda_runtime.h>

#define TT   2048
#define BB   2048
#define HH   32
#define DF   8
#define DS   24
#define GPB  4                 // 4-batch groups per block
#define NW   (GPB * 3)         // 12 warps: (A,B,C) x 4 groups
#define NTHR (NW * 32)         // 384 threads
#define NBLK (BB / (GPB * 4))  // 128 blocks

typedef unsigned long long u64;

__device__ __forceinline__ u64 dup2(float w) {
    u64 d; asm("mov.b64 %0, {%1, %1};" : "=l"(d) : "f"(w)); return d;
}
__device__ __forceinline__ void unpack2(u64 v, float &a, float &b) {
    asm("mov.b64 {%0, %1}, %2;" : "=f"(a), "=f"(b) : "l"(v));
}
__device__ __forceinline__ void fma2(u64 &acc, u64 a, u64 b) {
    asm("fma.rn.f32x2 %0, %1, %2, %0;" : "+l"(acc) : "l"(a), "l"(b));
}
__device__ __forceinline__ u64 add2(u64 x, u64 y) {
    u64 r; asm("add.rn.f32x2 %0, %1, %2;" : "=l"(r) : "l"(x), "l"(y)); return r;
}
__device__ __forceinline__ float tanh_fast(float x) {
    float e = __expf(2.0f * x);
    return 1.0f - __fdividef(2.0f, e + 1.0f);
}

struct GroupSW {
    float4 hA[HH];                 // h_f  (warp A private)
    float4 hB[HH];                 // h_p  (warp B private)
    float4 s0[HH], s1[HH], s2[HH]; // h_s rows (warp-private)
    float4 xA[DF], xB[DF];         // staged x_f / x_p
    float4 xC[DS];                 // staged x_s
};

__global__ void __launch_bounds__(NTHR, 1) chive_kernel(
    const float* __restrict__ frnn, const float* __restrict__ phrnn, const float* __restrict__ syl,
    const float* __restrict__ Wxf, const float* __restrict__ Whf, const float* __restrict__ bfv,
    const float* __restrict__ Wxp, const float* __restrict__ Whp, const float* __restrict__ bpv,
    const float* __restrict__ Wxs, const float* __restrict__ Whs, const float* __restrict__ bsv,
    const int* __restrict__ fclk, const int* __restrict__ pclk, const int* __restrict__ sfreq,
    float* __restrict__ out)
{
    __shared__ GroupSW sw[GPB];
    __shared__ unsigned char flags[TT];

    const int tid  = threadIdx.x;
    const int wid  = tid >> 5;
    const int lane = tid & 31;
    const int grp  = wid / 3;
    const int role = wid % 3;      // 0 = f-cell+row0, 1 = p-cell+row1, 2 = row2
    const int j    = lane;

    // ---- zero all state + staging ----
    for (int i = tid; i < (int)(sizeof(GroupSW) / 4) * GPB; i += NTHR)
        ((float*)sw)[i] = 0.0f;

    // ---- warp-uniform update masks, depend only on t ----
    for (int t = tid; t < TT; t += NTHR) {
        int uf = ((t % (fclk[t] + 1)) == 0) ? 1 : 0;
        int up = ((t % (pclk[t] + 1)) == 0) ? 1 : 0;
        int us = (sfreq[t] == 1) ? 1 : 0;
        flags[t] = (unsigned char)(uf | (up << 1) | (us << 2));
    }
    __syncthreads();

    GroupSW& G = sw[grp];
    const int b0 = (blockIdx.x * GPB + grp) * 4;   // this group's 4 batch rows

    // ---- syl weight column j (all roles) ----
    float wsh[HH];
#pragma unroll
    for (int i = 0; i < HH; i++) wsh[i] = Whs[i * HH + j];
    const float bs_ = bsv[j];

    float4* srow = (role == 0) ? G.s0 : (role == 1) ? G.s1 : G.s2;

    // cached partials (all roles): S = s @ Wh_s   (s = 0 initially)
    u64 S0 = 0, S1 = 0;

    if (role < 2) {
        // ============ warp A / B: clockwork cell + its syl row ====================
        const float* xsrc = (role == 0) ? frnn : phrnn;
        const float* Wx   = (role == 0) ? Wxf  : Wxp;
        const float* Wh   = (role == 0) ? Whf  : Whp;
        const float* bv   = (role == 0) ? bfv  : bpv;
        float4* hst       = (role == 0) ? G.hA : G.hB;
        float4* xbuf      = (role == 0) ? G.xA : G.xB;
        const unsigned bit = 1u << role;

        float wx[DF], wh[HH], wsx[HH];
#pragma unroll
        for (int k = 0; k < DF; k++) wx[k] = Wx[k * HH + j];
#pragma unroll
        for (int i = 0; i < HH; i++) { wh[i] = Wh[i * HH + j]; wsx[i] = Wxs[i * HH + j]; }
        const float bc = bv[j];

        // cached partials: Hh = h@Wh (0), c = bs + h@Wx_s (bs)
        u64 Hh0 = 0, Hh1 = 0;
        u64 c0 = dup2(bs_), c1 = dup2(bs_);

        // staging: lane -> batch (lane>>3), feature (lane&7)
        const float* px = xsrc + (size_t)(b0 + (lane >> 3)) * DF + (lane & 7);
        float* xd = (float*)xbuf + (lane & 7) * 4 + (lane >> 3);
        const size_t str = (size_t)BB * DF;

        unsigned fl = flags[0];
        float v = (fl & bit) ? px[0] : 0.0f;
        for (int t = 0; t < TT; t++) {
            const unsigned fln = (t + 1 < TT) ? (unsigned)flags[t + 1] : 0u;

            if (fl & bit) {                    // ---- clockwork cell update ----
                xd[0] = v;                     // stage x[t]
                __syncwarp();
                // critical path: x@Wx (8 LDS, 16 fma2) + cached Hh
                u64 a = dup2(bc), b = dup2(bc);
                const ulonglong2* xv = (const ulonglong2*)xbuf;
#pragma unroll
                for (int k = 0; k < DF; k++) {
                    ulonglong2 x = xv[k]; u64 wd = dup2(wx[k]);
                    fma2(a, x.x, wd); fma2(b, x.y, wd);
                }
                u64 ra = add2(a, Hh0), rb = add2(b, Hh1);
                float q0, q1, q2, q3; unpack2(ra, q0, q1); unpack2(rb, q2, q3);
                float4 nf = make_float4(tanh_fast(q0), tanh_fast(q1),
                                        tanh_fast(q2), tanh_fast(q3));
                __syncwarp();                  // WAR: x reads done before reuse; h write
                hst[j] = nf;
                __syncwarp();                  // new h visible to all lanes
                // tail: ONE 32-LDS stream over new h feeds BOTH Hh' and c'
                u64 ha = 0, hb = 0, hc = 0, hd = 0;      // Hh' chains
                u64 ca = dup2(bs_), cb = dup2(bs_), cc = 0, cd = 0;  // c' chains
                const ulonglong2* hv = (const ulonglong2*)hst;
#pragma unroll
                for (int i = 0; i < HH / 2; i++) {
                    ulonglong2 h = hv[i];
                    u64 w1 = dup2(wh[i]), w2 = dup2(wsx[i]);
                    fma2(ha, h.x, w1); fma2(hb, h.y, w1);
                    fma2(ca, h.x, w2); fma2(cb, h.y, w2);
                }
#pragma unroll
                for (int i = HH / 2; i < HH; i++) {
                    ulonglong2 h = hv[i];
                    u64 w1 = dup2(wh[i]), w2 = dup2(wsx[i]);
                    fma2(hc, h.x, w1); fma2(hd, h.y, w1);
                    fma2(cc, h.x, w2); fma2(cd, h.y, w2);
                }
                Hh0 = add2(ha, hc); Hh1 = add2(hb, hd);
                c0  = add2(ca, cc); c1  = add2(cb, cd);
            }
            if (fln & bit)                     // prefetch x[t+1] only if needed
                v = px[(size_t)(t + 1) * str];

            if (fl & 4) {                      // ---- syl row update ----
                // critical path: ZERO loads — tanh(c + S)
                u64 ra = add2(c0, S0), rb = add2(c1, S1);
                float q0, q1, q2, q3; unpack2(ra, q0, q1); unpack2(rb, q2, q3);
                float4 n = make_float4(tanh_fast(q0), tanh_fast(q1),
                                       tanh_fast(q2), tanh_fast(q3));
                __syncwarp();                  // WAR vs previous S' reads
                srow[j] = n;
                __syncwarp();                  // new s visible
                // tail: refresh S' = s_new @ Wh_s (32 LDS, 64 fma2)
                u64 e = 0, f = 0, g = 0, k2 = 0;
                const ulonglong2* rv = (const ulonglong2*)srow;
#pragma unroll
                for (int i = 0; i < HH / 2; i++) {
                    ulonglong2 h = rv[i]; u64 wd = dup2(wsh[i]);
                    fma2(e, h.x, wd); fma2(f, h.y, wd);
                }
#pragma unroll
                for (int i = HH / 2; i < HH; i++) {
                    ulonglong2 h = rv[i]; u64 wd = dup2(wsh[i]);
                    fma2(g, h.x, wd); fma2(k2, h.y, wd);
                }
                S0 = add2(e, g); S1 = add2(f, k2);
            }
            fl = fln;
        }
    } else {
        // ============ warp C: x_s-driven syl row ==================================
        float wsx[DS];
#pragma unroll
        for (int i = 0; i < DS; i++) wsx[i] = Wxs[i * HH + j];

        const int fl0 = lane, fl1 = lane + 32, fl2 = lane + 64;   // 96 scalars
        const float* p0 = syl + (size_t)(b0 + fl0 / 24) * DS + (fl0 % 24);
        const float* p1 = syl + (size_t)(b0 + fl1 / 24) * DS + (fl1 % 24);
        const float* p2 = syl + (size_t)(b0 + fl2 / 24) * DS + (fl2 % 24);
        float* d0 = (float*)G.xC + (fl0 % 24) * 4 + (fl0 / 24);
        float* d1 = (float*)G.xC + (fl1 % 24) * 4 + (fl1 / 24);
        float* d2 = (float*)G.xC + (fl2 % 24) * 4 + (fl2 / 24);
        const size_t str = (size_t)BB * DS;

        unsigned fl = flags[0];
        float v0 = 0.f, v1 = 0.f, v2 = 0.f;
        if (fl & 4) { v0 = p0[0]; v1 = p1[0]; v2 = p2[0]; }
        for (int t = 0; t < TT; t++) {
            const unsigned fln = (t + 1 < TT) ? (unsigned)flags[t + 1] : 0u;

            if (fl & 4) {
                d0[0] = v0; d1[0] = v1; d2[0] = v2;   // stage x_s[t]
                __syncwarp();
                // critical path: x-part (12 LDS, 48 fma2) + cached S
                u64 a = dup2(bs_), b = dup2(bs_), c = 0, d = 0;
                const ulonglong2* xv = (const ulonglong2*)G.xC;
#pragma unroll
                for (int i = 0; i < DS / 2; i++) {
                    ulonglong2 x = xv[i]; u64 wd = dup2(wsx[i]);
                    fma2(a, x.x, wd); fma2(b, x.y, wd);
                }
#pragma unroll
                for (int i = DS / 2; i < DS; i++) {
                    ulonglong2 x = xv[i]; u64 wd = dup2(wsx[i]);
                    fma2(c, x.x, wd); fma2(d, x.y, wd);
                }
                u64 ra = add2(add2(a, c), S0);
                u64 rb = add2(add2(b, d), S1);
                float q0, q1, q2, q3; unpack2(ra, q0, q1); unpack2(rb, q2, q3);
                float4 n = make_float4(tanh_fast(q0), tanh_fast(q1),
                                       tanh_fast(q2), tanh_fast(q3));
                __syncwarp();                  // x reads done; WAR vs prior S' reads
                srow[j] = n;
                __syncwarp();                  // new s visible
                // tail: refresh S'
                u64 e = 0, f = 0, g = 0, k2 = 0;
                const ulonglong2* rv = (const ulonglong2*)srow;
#pragma unroll
                for (int i = 0; i < HH / 2; i++) {
                    ulonglong2 h = rv[i]; u64 wd = dup2(wsh[i]);
                    fma2(e, h.x, wd); fma2(f, h.y, wd);
                }
#pragma unroll
                for (int i = HH / 2; i < HH; i++) {
                    ulonglong2 h = rv[i]; u64 wd = dup2(wsh[i]);
                    fma2(g, h.x, wd); fma2(k2, h.y, wd);
                }
                S0 = add2(e, g); S1 = add2(f, k2);
            }
            if (fln & 4) {                     // prefetch x_s[t+1] only if needed
                const size_t o = (size_t)(t + 1) * str;
                v0 = p0[o]; v1 = p1[o]; v2 = p2[o];
            }
            fl = fln;
        }
    }

    // ---- output: each warp writes its own h_s row ----
    {
        float4 vv = srow[j];
        out[((size_t)role * BB + b0 + 0) * HH + j] = vv.x;
        out[((size_t)role * BB + b0 + 1) * HH + j] = vv.y;
        out[((size_t)role * BB + b0 + 2) * HH + j] = vv.z;
        out[((size_t)role * BB + b0 + 3) * HH + j] = vv.w;
    }
}

extern "C" void kernel_launch(void* const* d_in, const int* in_sizes, int n_in,
                              void* d_out, int out_size)
{
    (void)in_sizes; (void)n_in; (void)out_size;
    chive_kernel<<<NBLK, NTHR>>>(
        (const float*)d_in[0],  (const float*)d_in[1],  (const float*)d_in[2],
        (const float*)d_in[3],  (const float*)d_in[4],  (const float*)d_in[5],
        (const float*)d_in[6],  (const float*)d_in[7],  (const float*)d_in[8],
        (const float*)d_in[9],  (const float*)d_in[10], (const float*)d_in[11],
        (const int*)d_in[12],   (const int*)d_in[13],   (const int*)d_in[14],
        (float*)d_out);
}